// round 5
// baseline (speedup 1.0000x reference)
#include <cuda_runtime.h>
#include <cuda_bf16.h>

// Problem constants (fixed by the reference's setup_inputs)
#define BQ 4096
#define NQ 128
#define FQ 64
#define HIST 1024      // ids in [0,1000); -1 padding handled via unsigned compare
#define TROWS 129      // counts range 0..128 inclusive
#define BPB 4          // batches per block
#define PSTRIDE 68     // padded pair-sum row stride (floats)

// MLP lookup table: T[c][g] = b2[g] + sum_f relu(c*w1[f]+b1[f]) * w2[g*F+f]
__device__ float g_table[TROWS * FQ];

// ---------------------------------------------------------------------------
// Kernel 1: build the 129x64 MLP table. Trivial (~0.5M FMA, ~1us).
// ---------------------------------------------------------------------------
__global__ void build_table_kernel(const float* __restrict__ w1,
                                   const float* __restrict__ b1,
                                   const float* __restrict__ w2,
                                   const float* __restrict__ b2) {
    const int c = blockIdx.x;    // count value 0..128
    const int g = threadIdx.x;   // output feature 0..63
    __shared__ float h[FQ];
    h[g] = fmaxf((float)c * w1[g] + b1[g], 0.0f);   // w1 shape (F,1) -> w1[f]
    __syncthreads();
    float acc = b2[g];
#pragma unroll
    for (int f = 0; f < FQ; f++) {
        acc += h[f] * w2[g * FQ + f];   // einsum 'bncf,gf->bncg' => w2[g, f]
    }
    g_table[c * FQ + g] = acc;
}

// ---------------------------------------------------------------------------
// Kernel 2 (fused): per-block packed histograms for 4 batches + pair-sum
// table build (overlapped), then fully-coalesced streaming float4 writes.
// Shared: hist 8KB + S 4.25KB + cnts 2KB = ~14.7KB.
// Hot loop per output float4: 1 LDS.128 + 1 STG.128 (+ rare L2 fallback).
// ---------------------------------------------------------------------------
__global__ __launch_bounds__(256)
void fused_kernel(const int* __restrict__ src,
                  const int* __restrict__ dst,
                  float* __restrict__ out) {
    __shared__ unsigned int hist[2][HIST];  // packs: b0.src[0:8) b0.dst[8:16) b1.src[16:24) b1.dst[24:32)
    __shared__ float S[16 * PSTRIDE];       // S[a*4+b] = T[a] + T[b]
    __shared__ uchar4 sc[BPB][NQ];          // (c_ss, c_sd, c_dd, c_ds)

    const int tid = threadIdx.x;

    // Zero histograms (8 words/thread).
    for (int idx = tid; idx < 2 * HIST; idx += 256) {
        (&hist[0][0])[idx] = 0u;
    }

    // Build pair-sum table: 16 rows x 16 float4 = 256 entries, 1 per thread.
    // Overlaps with the histogram atomics below (same pre-sync region).
    {
        const int r = tid >> 4;           // pair index -> (a = r>>2, b = r&3)
        const int q = tid & 15;           // float4 column
        const float4 ta = *(const float4*)(g_table + (r >> 2) * FQ + q * 4);
        const float4 tb = *(const float4*)(g_table + (r & 3) * FQ + q * 4);
        float4 v;
        v.x = ta.x + tb.x; v.y = ta.y + tb.y; v.z = ta.z + tb.z; v.w = ta.w + tb.w;
        *(float4*)&S[r * PSTRIDE + q * 4] = v;
    }

    // NOTE: hist zeroing must complete before atomics; the zeroing loop above
    // is done by the same threads that atomically update only after this sync.
    __syncthreads();

    // Histogram: 4 batches x 128 ids = 512 items, 2 per thread.
    int s_ids[2], d_ids[2];
#pragma unroll
    for (int it = 0; it < 2; it++) {
        const int idx = it * 256 + tid;
        const int lb = idx >> 7;             // local batch 0..3
        const int i  = idx & 127;
        const long long b = (long long)blockIdx.x * BPB + lb;
        const int s = src[b * NQ + i];
        const int d = dst[b * NQ + i];
        s_ids[it] = s; d_ids[it] = d;
        const int p  = lb >> 1;
        const int sh = (lb & 1) * 16;
        if ((unsigned)s < HIST) atomicAdd(&hist[p][s], 1u << sh);
        if ((unsigned)d < HIST) atomicAdd(&hist[p][d], 1u << (sh + 8));
    }
    __syncthreads();

    // Extract counts. Padded id (-1) -> zero counts (reference's
    // where(pad, 0, freq); MLP(0) still applied via table row 0).
#pragma unroll
    for (int it = 0; it < 2; it++) {
        const int idx = it * 256 + tid;
        const int lb = idx >> 7;
        const int i  = idx & 127;
        const int p  = lb >> 1;
        const int sh = (lb & 1) * 16;
        const int s = s_ids[it], d = d_ids[it];
        const unsigned hs = ((unsigned)s < HIST) ? hist[p][s] : 0u;
        const unsigned hd = ((unsigned)d < HIST) ? hist[p][d] : 0u;
        uchar4 c;
        c.x = (unsigned char)((hs >> sh)       & 0xFFu);  // c_ss
        c.y = (unsigned char)((hs >> (sh + 8)) & 0xFFu);  // c_sd
        c.z = (unsigned char)((hd >> (sh + 8)) & 0xFFu);  // c_dd
        c.w = (unsigned char)((hd >> sh)       & 0xFFu);  // c_ds
        sc[lb][i] = c;
    }
    __syncthreads();

    // Streaming write: 4 batches x 2 halves x 2048 float4, coalesced.
    const int g4 = (tid & 15) * 4;
    const size_t halfq = (size_t)BQ * (NQ * FQ / 4);
#pragma unroll
    for (int lb = 0; lb < BPB; lb++) {
        const size_t b = (size_t)blockIdx.x * BPB + lb;
        float4* const osrc = (float4*)out + b * (NQ * FQ / 4);
        float4* const odst = osrc + halfq;
#pragma unroll
        for (int k = 0; k < 8; k++) {
            const int lin = k * 256 + tid;
            const int i   = lin >> 4;
            const uchar4 c = sc[lb][i];   // 16 lanes broadcast the same word

            // src_feat = T[c_ss] + T[c_sd]
            float4 a;
            if (((int)c.x | (int)c.y) < 4) {
                a = *(const float4*)&S[((int)c.x * 4 + (int)c.y) * PSTRIDE + g4];
            } else {
                const float4 u = *(const float4*)(g_table + (int)c.x * FQ + g4);
                const float4 v = *(const float4*)(g_table + (int)c.y * FQ + g4);
                a.x = u.x + v.x; a.y = u.y + v.y; a.z = u.z + v.z; a.w = u.w + v.w;
            }
            __stcs(&osrc[lin], a);

            // dst_feat = T[c_dd] + T[c_ds]
            float4 e;
            if (((int)c.z | (int)c.w) < 4) {
                e = *(const float4*)&S[((int)c.z * 4 + (int)c.w) * PSTRIDE + g4];
            } else {
                const float4 u = *(const float4*)(g_table + (int)c.z * FQ + g4);
                const float4 v = *(const float4*)(g_table + (int)c.w * FQ + g4);
                e.x = u.x + v.x; e.y = u.y + v.y; e.z = u.z + v.z; e.w = u.w + v.w;
            }
            __stcs(&odst[lin], e);
        }
    }
}

// ---------------------------------------------------------------------------
// Launch. Inputs (metadata order): src_ids[B*N] i32, dst_ids[B*N] i32,
// w1[F] f32, b1[F] f32, w2[F*F] f32, b2[F] f32. Output: f32, 2*B*N*F
// (src_feat flattened, then dst_feat flattened).
// ---------------------------------------------------------------------------
extern "C" void kernel_launch(void* const* d_in, const int* in_sizes, int n_in,
                              void* d_out, int out_size) {
    const int*   src = (const int*)d_in[0];
    const int*   dst = (const int*)d_in[1];
    const float* w1  = (const float*)d_in[2];
    const float* b1  = (const float*)d_in[3];
    const float* w2  = (const float*)d_in[4];
    const float* b2  = (const float*)d_in[5];
    float* out = (float*)d_out;

    build_table_kernel<<<TROWS, FQ>>>(w1, b1, w2, b2);
    fused_kernel<<<BQ / BPB, 256>>>(src, dst, out);
}